// round 14
// baseline (speedup 1.0000x reference)
#include <cuda_runtime.h>

// EMA over time axis of wave[B=4096, T=6000, C=3], fp32.
//   sta_t = sta_{t-1} + W*(x_t - sta_{t-1}),  sta_{-1} = 0
// Contractive recurrence (decay A = 1-W = 0.4): 0.4^24 ~ 2.8e-10, so each
// time chunk's carry-in is reconstructed from J=24 warmup samples.
// Shared-memory staging gives fully coalesced global traffic; walkers scan
// serially in smem with a bank-conflict-free pitch (PITCH % 32 == 3).

constexpr int   CH  = 3;
constexpr int   L   = 250;                 // time steps per chunk (6000 = 24*250)
constexpr int   J   = 24;                  // warmup steps
constexpr int   R   = 32;                  // rows (batch entries) per block
constexpr int   TILE_W = CH * (L + J);     // 822 valid words per row
constexpr int   PITCH  = 835;              // 822 + 13 pad; 835 % 32 == 3
static_assert(PITCH % 32 == 3, "bank-conflict-free walker layout requires pitch%32==3");
constexpr int   SMEM_BYTES = R * PITCH * 4;   // 106,880 B -> 2 CTAs/SM
constexpr int   THREADS = 256;
constexpr float Wc = 0.6f;
constexpr float Ac = 1.0f - Wc;            // 0.4

__global__ __launch_bounds__(THREADS, 2)
void ema_scan_kernel(const float* __restrict__ wave,
                     float* __restrict__ out,
                     int B, int T)
{
    extern __shared__ float tile[];
    const int tid   = threadIdx.x;
    const int chunk = blockIdx.x;
    const int b0    = blockIdx.y * R;
    const int t0    = chunk * L;
    const long long rowStride = (long long)T * CH;

    // ---- cooperative coalesced load: rows [b0,b0+R), times [t0-J, t0+L) ----
    const int tl0 = t0 - J;   // may be negative for chunk 0 -> zeros (== zero init)
    for (int idx = tid; idx < R * TILE_W; idx += THREADS) {
        const int row = idx / TILE_W;                // constexpr divisor
        const int col = idx - row * TILE_W;
        const int t   = tl0 + col / CH;
        const int b   = b0 + row;
        float v = 0.0f;
        if (t >= 0 && t < T && b < B)
            v = wave[(long long)b * rowStride + (long long)t * CH + (col - (col / CH) * CH)];
        tile[row * PITCH + col] = v;
    }
    __syncthreads();

    // ---- serial EMA walkers: one thread per (row, channel), in-place in smem ----
    const int steps = min(L, T - t0);                // == L for this shape
    if (tid < R * CH) {
        const int row = tid / CH;
        const int c   = tid - row * CH;
        float* p = tile + row * PITCH + c;
        float sta = 0.0f;
        #pragma unroll
        for (int j = 0; j < J; ++j)
            sta = fmaf(Ac, sta, Wc * p[j * CH]);
        #pragma unroll 4
        for (int i = 0; i < steps; ++i) {
            const float x = p[(J + i) * CH];
            sta = fmaf(Ac, sta, Wc * x);
            p[(J + i) * CH] = sta;
        }
    }
    __syncthreads();

    // ---- cooperative coalesced store: times [t0, t0+steps) ----
    if (steps == L) {
        constexpr int OUTW = CH * L;                 // 750, constexpr divisor
        for (int idx = tid; idx < R * OUTW; idx += THREADS) {
            const int row = idx / OUTW;
            const int col = idx - row * OUTW;
            const int b = b0 + row;
            if (b < B)
                out[(long long)b * rowStride + (long long)t0 * CH + col] =
                    tile[row * PITCH + CH * J + col];
        }
    } else {
        const int outW = CH * steps;
        for (int idx = tid; idx < R * outW; idx += THREADS) {
            const int row = idx / outW;
            const int col = idx - row * outW;
            const int b = b0 + row;
            if (b < B)
                out[(long long)b * rowStride + (long long)t0 * CH + col] =
                    tile[row * PITCH + CH * J + col];
        }
    }
}

extern "C" void kernel_launch(void* const* d_in, const int* in_sizes, int n_in,
                              void* d_out, int out_size)
{
    const float* wave = (const float*)d_in[0];
    float*       out  = (float*)d_out;

    const int T = 6000;
    const int B = in_sizes[0] / (T * CH);            // 4096

    // Idempotent, deterministic, not a stream op -> graph-capture safe.
    cudaFuncSetAttribute(ema_scan_kernel,
                         cudaFuncAttributeMaxDynamicSharedMemorySize, SMEM_BYTES);

    dim3 grid((T + L - 1) / L, (B + R - 1) / R);     // 24 x 128 = 3072 blocks
    ema_scan_kernel<<<grid, THREADS, SMEM_BYTES>>>(wave, out, B, T);
}

// round 15
// speedup vs baseline: 2.5472x; 2.5472x over previous
#include <cuda_runtime.h>

// EMA recurrence over time for wave[B=4096, T=6000, C=3], fp32:
//   sta_t = sta_{t-1} + W*(x_t - sta_{t-1}),  sta_{-1} = 0,  W = 0.6
// Decay A = 0.4 is strongly contractive: 0.4^24 ~ 2.8e-10 << fp32 eps, so any
// position's state is reconstructible from the previous J=24 samples. This
// breaks both the inter-chunk dependence (blocks) and intra-chunk dependence
// (sub-chunk walkers, warming up from data already in smem).
//
// Layout choices:
//  * L=500 time steps/chunk -> 3L=1500 and 3(t0-J)=1500c-72 are both multiples
//    of 4, so ALL global segments are float4-aligned. 12 chunks cover T=6000.
//  * One warp copies one row: fully unrolled float4 loops, no division,
//    13 back-to-back LDG.128 per thread -> deep MLP.
//  * R=8 rows/block, smem = 50,304 B -> 4 CTAs/SM (32 warps), so copy phases
//    overlap other CTAs' walker phases.
//  * 5 sub-chunks of S=100 per chunk -> 120 concurrent walkers/block, serial
//    chain only 124 FMAs. Warmup(all) -> __syncthreads -> main(in-place)
//    keeps the in-place smem update race-free.

constexpr int   CH   = 3;
constexpr int   L    = 500;                // steps per chunk (6000 = 12*500)
constexpr int   J    = 24;                 // warmup steps (0.4^24 ~ 2.8e-10)
constexpr int   R    = 8;                  // rows per block (one per warp)
constexpr int   NSUB = 5;                  // sub-chunks per chunk
constexpr int   S    = L / NSUB;           // 100 steps per walker
constexpr int   ROWF = CH * (L + J);       // 1572 floats per smem row
constexpr int   ROWV = ROWF / 4;           // 393 float4 per row
constexpr int   OUTV = CH * L / 4;         // 375 float4 output per row
constexpr int   WALK = R * NSUB * CH;      // 120 walker threads
constexpr int   THREADS = 256;
constexpr int   SMEM_BYTES = R * ROWF * 4; // 50,304 B -> 4 CTAs/SM
constexpr float Wc = 0.6f;
constexpr float Ac = 1.0f - Wc;            // 0.4

constexpr int LD_ITERS = (ROWV + 31) / 32; // 13
constexpr int ST_ITERS = (OUTV + 31) / 32; // 12

__global__ __launch_bounds__(THREADS, 4)
void ema_scan_kernel(const float4* __restrict__ w4, float4* __restrict__ o4)
{
    extern __shared__ float tile[];
    float4* tile4 = reinterpret_cast<float4*>(tile);

    const int tid   = threadIdx.x;
    const int lane  = tid & 31;
    const int warp  = tid >> 5;            // 0..7 == row within block
    const int chunk = blockIdx.x;          // 0..11
    const int b     = blockIdx.y * R + warp;

    // ---- load: row 'warp', float4 segment [src0, src0+393) ----
    // src0 (float4 units) = (b*18000 + (500*chunk - 24)*3) / 4
    const int src0 = b * 4500 + chunk * 375 - 18;
    float4* trow = tile4 + warp * ROWV;
    if (chunk > 0) {
        #pragma unroll
        for (int it = 0; it < LD_ITERS; ++it) {
            const int j = lane + it * 32;
            if (j < ROWV) trow[j] = w4[src0 + j];
        }
    } else {
        // chunk 0: first 18 float4 (= J*3 floats) are the zero initial state
        #pragma unroll
        for (int it = 0; it < LD_ITERS; ++it) {
            const int j = lane + it * 32;
            if (j < ROWV)
                trow[j] = (j >= 18) ? w4[src0 + j] : make_float4(0.f, 0.f, 0.f, 0.f);
        }
    }
    __syncthreads();

    // ---- walkers: warmup phase (reads only raw x, no writes) ----
    float sta = 0.0f;
    float* p  = nullptr;
    int   mb  = 0;
    if (tid < WALK) {
        const int r = tid / (NSUB * CH);   // row
        const int q = tid % (NSUB * CH);
        const int s = q / CH;              // sub-chunk
        const int c = q % CH;              // channel
        float* rowp = tile + r * ROWF;
        const int wb = s * (S * CH) + c;   // warmup base: 24 steps before main
        #pragma unroll
        for (int j = 0; j < J; ++j)
            sta = fmaf(Ac, sta, Wc * rowp[wb + 3 * j]);
        p  = rowp;
        mb = J * CH + s * (S * CH) + c;    // main base
    }
    __syncthreads();   // all warmup reads complete before any in-place write

    // ---- walkers: main phase (each walker owns a disjoint region) ----
    if (tid < WALK) {
        #pragma unroll 4
        for (int i = 0; i < S; ++i) {
            const float x = p[mb + 3 * i];
            sta = fmaf(Ac, sta, Wc * x);
            p[mb + 3 * i] = sta;
        }
    }
    __syncthreads();

    // ---- store: row 'warp', output segment [dst0, dst0+375) ----
    const int dst0 = b * 4500 + chunk * 375;
    const float4* srow = tile4 + warp * ROWV + J * CH / 4;   // skip 18 prefix
    #pragma unroll
    for (int it = 0; it < ST_ITERS; ++it) {
        const int j = lane + it * 32;
        if (j < OUTV) o4[dst0 + j] = srow[j];
    }
}

extern "C" void kernel_launch(void* const* d_in, const int* in_sizes, int n_in,
                              void* d_out, int out_size)
{
    const float4* w4 = (const float4*)d_in[0];
    float4*       o4 = (float4*)d_out;

    const int T = 6000;
    const int B = in_sizes[0] / (T * CH);   // 4096

    cudaFuncSetAttribute(ema_scan_kernel,
                         cudaFuncAttributeMaxDynamicSharedMemorySize, SMEM_BYTES);

    dim3 grid(T / L, B / R);                // 12 x 512 = 6144 blocks
    ema_scan_kernel<<<grid, THREADS, SMEM_BYTES>>>(w4, o4);
}

// round 16
// speedup vs baseline: 3.3745x; 1.3248x over previous
#include <cuda_runtime.h>
#include <cstdint>

// EMA over time for wave[B=4096, T=6000, C=3], fp32:
//   sta_t = sta_{t-1} + W*(x_t - sta_{t-1}),  sta_{-1}=0,  W=0.6
// Decay 0.4^24 ~ 2.8e-10 << fp32 eps -> any chunk/sub-chunk carry-in is
// reconstructible from J=24 warmup samples.
//
// R16 design: all global<->smem movement via 1D TMA bulk copies (UBLKCP,
// L2<->smem, zero L1tex wavefronts); walkers own (row, sub-chunk) with all
// 3 channels so the serial scan streams contiguous float4 in smem (4 time
// steps per 3 LDS.128/STS.128, ILP-3 FMA chains).

constexpr int CH   = 3;
constexpr int L    = 500;                 // 6000 = 12 * 500
constexpr int J    = 24;                  // warmup steps
constexpr int R    = 8;                   // rows per block
constexpr int NSUB = 5;                   // sub-chunks (S*CH must be %4==0)
constexpr int S    = L / NSUB;            // 100 steps per walker
constexpr int ROWF = CH * (L + J);        // 1572 floats
constexpr int ROWV = ROWF / 4;            // 393 float4
constexpr int ROWBYTES = ROWF * 4;        // 6288 (16B multiple)
constexpr int OUTBYTES = CH * L * 4;      // 6000 (16B multiple)
constexpr int SMEM_BYTES = R * ROWBYTES;  // 50304 -> 4 CTAs/SM
constexpr int THREADS = 64;
constexpr float Wc  = 0.6f;
constexpr float Acf = 0.4f;

__device__ __forceinline__ uint32_t smem_u32(const void* p) {
    return (uint32_t)__cvta_generic_to_shared(p);
}

#define EMA3(x0, x1, x2)                      \
    s0 = fmaf(Acf, s0, Wc * (x0));            \
    s1 = fmaf(Acf, s1, Wc * (x1));            \
    s2 = fmaf(Acf, s2, Wc * (x2));

__global__ __launch_bounds__(THREADS, 4)
void ema_scan_kernel(const float* __restrict__ wave, float* __restrict__ out)
{
    extern __shared__ float tile[];
    __shared__ uint64_t mbar;
    float4* tile4 = reinterpret_cast<float4*>(tile);

    const int tid   = threadIdx.x;
    const int chunk = blockIdx.x;            // 0..11
    const int b0    = blockIdx.y * R;

    const uint32_t m = smem_u32(&mbar);
    if (tid == 0)
        asm volatile("mbarrier.init.shared::cta.b64 [%0], 1;" :: "r"(m) : "memory");

    // chunk 0: prefix [t0-24, t0) doesn't exist; zero it (== zero init state)
    if (chunk == 0) {
        for (int i = tid; i < R * (J * CH / 4); i += THREADS) {
            const int r = i / (J * CH / 4);
            const int j = i % (J * CH / 4);
            tile4[r * ROWV + j] = make_float4(0.f, 0.f, 0.f, 0.f);
        }
    }
    __syncthreads();   // mbar init + zero-fill visible

    // ---- TMA bulk loads: one contiguous segment per row ----
    if (tid == 0) {
        const uint32_t rowBytes = (chunk == 0) ? (uint32_t)OUTBYTES : (uint32_t)ROWBYTES;
        asm volatile("mbarrier.arrive.expect_tx.shared::cta.b64 _, [%0], %1;"
                     :: "r"(m), "r"(rowBytes * R) : "memory");
        #pragma unroll
        for (int r = 0; r < R; ++r) {
            const float* src = wave + (size_t)(b0 + r) * 18000
                                    + (size_t)chunk * 1500 - 72;
            uint32_t dst = smem_u32(tile + r * ROWF);
            if (chunk == 0) { src += 72; dst += J * CH * 4; }
            asm volatile(
                "cp.async.bulk.shared::cluster.global.mbarrier::complete_tx::bytes"
                " [%0], [%1], %2, [%3];"
                :: "r"(dst), "l"(src), "r"(rowBytes), "r"(m) : "memory");
        }
    }
    // all threads wait for data (acquire)
    asm volatile(
        "{\n\t.reg .pred P;\n\t"
        "W_%=:\n\t"
        "mbarrier.try_wait.parity.acquire.cta.shared::cta.b64 P, [%0], 0;\n\t"
        "@!P bra W_%=;\n\t}"
        :: "r"(m) : "memory");

    // ---- walkers: (row, sub-chunk), all 3 channels, float4 streaming ----
    float s0 = 0.f, s1 = 0.f, s2 = 0.f;
    float4* base = nullptr;
    if (tid < R * NSUB) {
        const int r = tid / NSUB;
        const int s = tid % NSUB;
        base = tile4 + r * ROWV + (J * CH / 4) + s * (S * CH / 4);
        const float4* wu = base - (J * CH / 4);   // 18 f4 = 24 warmup steps
        #pragma unroll
        for (int g = 0; g < (J * CH) / 12; ++g) {     // 6 groups of 4 steps
            const float4 a = wu[3 * g + 0];
            const float4 b = wu[3 * g + 1];
            const float4 c = wu[3 * g + 2];
            EMA3(a.x, a.y, a.z)  EMA3(a.w, b.x, b.y)
            EMA3(b.z, b.w, c.x)  EMA3(c.y, c.z, c.w)
        }
    }
    __syncthreads();   // warmup reads (into s>0 neighbors' regions) done before writes

    if (tid < R * NSUB) {
        #pragma unroll 5
        for (int g = 0; g < (S * CH) / 12; ++g) {     // 25 groups of 4 steps
            float4 a = base[3 * g + 0];
            float4 b = base[3 * g + 1];
            float4 c = base[3 * g + 2];
            s0 = fmaf(Acf, s0, Wc * a.x); a.x = s0;
            s1 = fmaf(Acf, s1, Wc * a.y); a.y = s1;
            s2 = fmaf(Acf, s2, Wc * a.z); a.z = s2;
            s0 = fmaf(Acf, s0, Wc * a.w); a.w = s0;
            s1 = fmaf(Acf, s1, Wc * b.x); b.x = s1;
            s2 = fmaf(Acf, s2, Wc * b.y); b.y = s2;
            s0 = fmaf(Acf, s0, Wc * b.z); b.z = s0;
            s1 = fmaf(Acf, s1, Wc * b.w); b.w = s1;
            s2 = fmaf(Acf, s2, Wc * c.x); c.x = s2;
            s0 = fmaf(Acf, s0, Wc * c.y); c.y = s0;
            s1 = fmaf(Acf, s1, Wc * c.z); c.z = s1;
            s2 = fmaf(Acf, s2, Wc * c.w); c.w = s2;
            base[3 * g + 0] = a;
            base[3 * g + 1] = b;
            base[3 * g + 2] = c;
        }
    }
    __syncthreads();   // all results in smem

    // ---- TMA bulk stores: one contiguous segment per row ----
    if (tid == 0) {
        asm volatile("fence.proxy.async.shared::cta;" ::: "memory");
        #pragma unroll
        for (int r = 0; r < R; ++r) {
            float* dst = out + (size_t)(b0 + r) * 18000 + (size_t)chunk * 1500;
            uint32_t src = smem_u32(tile + r * ROWF + J * CH);
            asm volatile(
                "cp.async.bulk.global.shared::cta.bulk_group [%0], [%1], %2;"
                :: "l"(dst), "r"(src), "r"((uint32_t)OUTBYTES) : "memory");
        }
        asm volatile("cp.async.bulk.commit_group;" ::: "memory");
        asm volatile("cp.async.bulk.wait_group 0;" ::: "memory");
    }
}

extern "C" void kernel_launch(void* const* d_in, const int* in_sizes, int n_in,
                              void* d_out, int out_size)
{
    const float* wave = (const float*)d_in[0];
    float*       out  = (float*)d_out;

    const int T = 6000;
    const int B = in_sizes[0] / (T * CH);    // 4096

    cudaFuncSetAttribute(ema_scan_kernel,
                         cudaFuncAttributeMaxDynamicSharedMemorySize, SMEM_BYTES);

    dim3 grid(T / L, B / R);                 // 12 x 512 = 6144 blocks
    ema_scan_kernel<<<grid, THREADS, SMEM_BYTES>>>(wave, out);
}

// round 17
// speedup vs baseline: 3.4718x; 1.0289x over previous
#include <cuda_runtime.h>
#include <cstdint>

// EMA over time for wave[B=4096, T=6000, C=3], fp32:
//   sta_t = sta_{t-1} + W*(x_t - sta_{t-1}),  sta_{-1}=0,  W=0.6
// Decay 0.4^24 ~ 2.8e-10 << fp32 eps -> chunk/sub-chunk carry-ins are
// reconstructible from J=24 warmup samples.
//
// R17: double-buffered CTA pipeline. Each CTA owns 4 rows x 2 consecutive
// chunks (two 25.2 KB stages). Both TMA bulk-load batches are issued up
// front; stage-0 compute overlaps stage-1 load; stage-0 bulk store overlaps
// stage-1 compute. 4 CTAs/SM -> 8 stage-pipelines per SM keeps HBM saturated.

constexpr int CH   = 3;
constexpr int L    = 500;                 // 6000 = 12 * 500
constexpr int J    = 24;                  // warmup steps
constexpr int R    = 4;                   // rows per stage
constexpr int NSUB = 5;                   // sub-chunks; S*CH % 4 == 0
constexpr int S    = L / NSUB;            // 100
constexpr int ROWF = CH * (L + J);        // 1572 floats
constexpr int ROWV = ROWF / 4;            // 393 float4
constexpr int ROWBYTES = ROWF * 4;        // 6288
constexpr int OUTBYTES = CH * L * 4;      // 6000
constexpr int STAGEF   = R * ROWF;        // 6288 floats / stage
constexpr int SMEM_BYTES = 2 * STAGEF * 4;// 50304 -> 4 CTAs/SM
constexpr int THREADS = 64;
constexpr float Wc  = 0.6f;
constexpr float Acf = 0.4f;

__device__ __forceinline__ uint32_t smem_u32(const void* p) {
    return (uint32_t)__cvta_generic_to_shared(p);
}

#define EMA3(x0, x1, x2)                      \
    s0 = fmaf(Acf, s0, Wc * (x0));            \
    s1 = fmaf(Acf, s1, Wc * (x1));            \
    s2 = fmaf(Acf, s2, Wc * (x2));

__device__ __forceinline__ void issue_loads(float* stg, uint32_t m, int c,
                                            int b0, const float* __restrict__ wave)
{
    const uint32_t bytes = (c == 0) ? (uint32_t)OUTBYTES : (uint32_t)ROWBYTES;
    asm volatile("mbarrier.arrive.expect_tx.shared::cta.b64 _, [%0], %1;"
                 :: "r"(m), "r"(bytes * R) : "memory");
    #pragma unroll
    for (int r = 0; r < R; ++r) {
        const float* src = wave + (size_t)(b0 + r) * 18000 + (size_t)c * 1500 - 72;
        uint32_t dst = smem_u32(stg + r * ROWF);
        if (c == 0) { src += 72; dst += J * CH * 4; }
        asm volatile(
            "cp.async.bulk.shared::cluster.global.mbarrier::complete_tx::bytes"
            " [%0], [%1], %2, [%3];"
            :: "r"(dst), "l"(src), "r"(bytes), "r"(m) : "memory");
    }
}

__device__ __forceinline__ void wait_mbar(uint32_t m)
{
    asm volatile(
        "{\n\t.reg .pred P;\n\t"
        "W_%=:\n\t"
        "mbarrier.try_wait.parity.acquire.cta.shared::cta.b64 P, [%0], 0;\n\t"
        "@!P bra W_%=;\n\t}"
        :: "r"(m) : "memory");
}

// All 64 threads enter (contains __syncthreads). Walkers: tid < R*NSUB = 20.
__device__ __forceinline__ void compute_stage(float* stg, int tid)
{
    float4* t4 = reinterpret_cast<float4*>(stg);
    float s0 = 0.f, s1 = 0.f, s2 = 0.f;
    float4* base = nullptr;
    if (tid < R * NSUB) {
        const int r = tid / NSUB;
        const int s = tid % NSUB;
        base = t4 + r * ROWV + (J * CH / 4) + s * (S * CH / 4);
        const float4* wu = base - (J * CH / 4);      // 18 f4 = 24 warmup steps
        #pragma unroll
        for (int g = 0; g < (J * CH) / 12; ++g) {    // 6 groups of 4 steps
            const float4 a = wu[3 * g + 0];
            const float4 b = wu[3 * g + 1];
            const float4 c = wu[3 * g + 2];
            EMA3(a.x, a.y, a.z)  EMA3(a.w, b.x, b.y)
            EMA3(b.z, b.w, c.x)  EMA3(c.y, c.z, c.w)
        }
    }
    __syncthreads();   // warmup reads of raw x finish before in-place writes
    if (tid < R * NSUB) {
        #pragma unroll 5
        for (int g = 0; g < (S * CH) / 12; ++g) {    // 25 groups of 4 steps
            float4 a = base[3 * g + 0];
            float4 b = base[3 * g + 1];
            float4 c = base[3 * g + 2];
            s0 = fmaf(Acf, s0, Wc * a.x); a.x = s0;
            s1 = fmaf(Acf, s1, Wc * a.y); a.y = s1;
            s2 = fmaf(Acf, s2, Wc * a.z); a.z = s2;
            s0 = fmaf(Acf, s0, Wc * a.w); a.w = s0;
            s1 = fmaf(Acf, s1, Wc * b.x); b.x = s1;
            s2 = fmaf(Acf, s2, Wc * b.y); b.y = s2;
            s0 = fmaf(Acf, s0, Wc * b.z); b.z = s0;
            s1 = fmaf(Acf, s1, Wc * b.w); b.w = s1;
            s2 = fmaf(Acf, s2, Wc * c.x); c.x = s2;
            s0 = fmaf(Acf, s0, Wc * c.y); c.y = s0;
            s1 = fmaf(Acf, s1, Wc * c.z); c.z = s1;
            s2 = fmaf(Acf, s2, Wc * c.w); c.w = s2;
            base[3 * g + 0] = a;
            base[3 * g + 1] = b;
            base[3 * g + 2] = c;
        }
    }
    __syncthreads();   // results visible to the async proxy (store follows)
}

__device__ __forceinline__ void issue_stores(float* stg, int c, int b0,
                                             float* __restrict__ out)
{
    asm volatile("fence.proxy.async.shared::cta;" ::: "memory");
    #pragma unroll
    for (int r = 0; r < R; ++r) {
        float* dst = out + (size_t)(b0 + r) * 18000 + (size_t)c * 1500;
        uint32_t src = smem_u32(stg + r * ROWF + J * CH);
        asm volatile(
            "cp.async.bulk.global.shared::cta.bulk_group [%0], [%1], %2;"
            :: "l"(dst), "r"(src), "r"((uint32_t)OUTBYTES) : "memory");
    }
    asm volatile("cp.async.bulk.commit_group;" ::: "memory");
}

__global__ __launch_bounds__(THREADS, 4)
void ema_scan_kernel(const float* __restrict__ wave, float* __restrict__ out)
{
    extern __shared__ float tile[];
    __shared__ uint64_t mbar[2];

    const int tid = threadIdx.x;
    const int c0  = 2 * blockIdx.x;          // chunks c0, c0+1 (0..11)
    const int c1  = c0 + 1;
    const int b0  = blockIdx.y * R;

    float* stage0 = tile;
    float* stage1 = tile + STAGEF;
    const uint32_t m0 = smem_u32(&mbar[0]);
    const uint32_t m1 = smem_u32(&mbar[1]);

    if (tid == 0) {
        asm volatile("mbarrier.init.shared::cta.b64 [%0], 1;" :: "r"(m0) : "memory");
        asm volatile("mbarrier.init.shared::cta.b64 [%0], 1;" :: "r"(m1) : "memory");
    }
    if (c0 == 0) {
        // zero the 18-float4 prefix of each stage-0 row (== zero initial state)
        for (int i = tid; i < R * (J * CH / 4); i += THREADS) {
            const int r = i / (J * CH / 4);
            const int j = i % (J * CH / 4);
            reinterpret_cast<float4*>(stage0)[r * ROWV + j] =
                make_float4(0.f, 0.f, 0.f, 0.f);
        }
    }
    __syncthreads();   // mbar init + zero-fill visible before loads / waits

    if (tid == 0) {
        issue_loads(stage0, m0, c0, b0, wave);   // both stages stream
        issue_loads(stage1, m1, c1, b0, wave);   // concurrently
    }

    wait_mbar(m0);
    compute_stage(stage0, tid);
    if (tid == 0) issue_stores(stage0, c0, b0, out);   // async, overlaps stage 1

    wait_mbar(m1);
    compute_stage(stage1, tid);
    if (tid == 0) {
        issue_stores(stage1, c1, b0, out);
        asm volatile("cp.async.bulk.wait_group 0;" ::: "memory");  // smem safe
    }
}

extern "C" void kernel_launch(void* const* d_in, const int* in_sizes, int n_in,
                              void* d_out, int out_size)
{
    const float* wave = (const float*)d_in[0];
    float*       out  = (float*)d_out;

    const int T = 6000;
    const int B = in_sizes[0] / (T * CH);    // 4096

    cudaFuncSetAttribute(ema_scan_kernel,
                         cudaFuncAttributeMaxDynamicSharedMemorySize, SMEM_BYTES);

    dim3 grid(T / (2 * L), B / R);           // 6 x 1024 = 6144 blocks
    ema_scan_kernel<<<grid, THREADS, SMEM_BYTES>>>(wave, out);
}